// round 7
// baseline (speedup 1.0000x reference)
#include <cuda_runtime.h>
#include <math.h>

// Problem constants
#define Bz 64
#define Hd 512
#define Sl 64
#define Tt 32
#define BH (Bz*Hd)
#define NB 128

// Output layout
#define OFF_AT 1048576
#define OFF_HF 1179648
#define OFF_CF 1245184
#define OFF_FF 1310720

// ---------------------------------------------------------------------------
// Persistent state. ALL cross-block traffic goes through __ldcg/__stcg
// (L1-bypass), so the grid barrier needs no CCTL-emitting fences and
// read-only weights stay L1-resident across all 32 steps.
// ---------------------------------------------------------------------------
__device__ float g_h0[2][BH], g_h1[2][BH];
__device__ float g_feed[BH], g_cvec[BH];
__device__ float g_ctxW[Sl*Bz*Hd];    // [s][b][j] = sum_k ctx[s,b,k]*Wa[k,j]
__device__ float g_g0[4][Bz*4*Hd];    // gates0 split-K partials
__device__ float g_g1[4][Bz*4*Hd];    // gates1 split-K partials
__device__ float g_op[16][BH];        // Wout partials
__device__ unsigned g_barcnt = 0u;
__device__ unsigned g_bargen = 0u;

__device__ __forceinline__ float sigf(float x){ return 1.0f/(1.0f+__expf(-x)); }

// Grid barrier with acquire/release atomics (no membar.gl -> no L1 flush).
__device__ __forceinline__ void gridbar_to(unsigned target){
    __syncthreads();
    if (threadIdx.x == 0){
        unsigned old;
        asm volatile("atom.acq_rel.gpu.global.add.u32 %0, [%1], 1;"
                     : "=r"(old) : "l"(&g_barcnt) : "memory");
        if (old == (unsigned)(NB-1)){
            g_barcnt = 0u;   // ordered before the release store below
            asm volatile("st.release.gpu.global.u32 [%0], %1;"
                         :: "l"(&g_bargen), "r"(target) : "memory");
        } else {
            unsigned g;
            do {
                asm volatile("ld.acquire.gpu.global.u32 %0, [%1];"
                             : "=r"(g) : "l"(&g_bargen) : "memory");
            } while (g != target);
        }
    }
    __syncthreads();
}

// ---------------------------------------------------------------------------
// 64b x 64j tile GEMM, 256 threads, micro-tile 4b x 4j (16 accums).
// K chunks of 32, register prefetch. Loaders: lane = row (l and l+32),
// warp selects k-quad -> conflict-free STS.32 with row pad 68.
// fx(c,r): row-base pointer of x row r at chunk c's kbase (loaded via ldcg).
// fw(c,r): LDW==1: W row pointer at kbase (float4 along k, via ldg).
//          else   : pointer to element (kbase, col=r), stride LDW along k.
// ---------------------------------------------------------------------------
template<int LDW, class FX, class FW>
__device__ __forceinline__ void tile_gemm44(float (&a)[4][4], FX fx, FW fw, int nch,
                                            float (*xs)[68], float (*ws)[68])
{
    const int tid = threadIdx.x;
    const int tb4 = (tid >> 4) << 2;
    const int tj4 = (tid & 15) << 2;
    const int ln  = tid & 31;
    const int k4  = (tid >> 5) << 2;
    float4 x0, x1;
    float  w0[4], w1[4];

    {   // prefetch chunk 0
        x0 = __ldcg((const float4*)(fx(0, ln)    + k4));
        x1 = __ldcg((const float4*)(fx(0, ln+32) + k4));
        if constexpr (LDW == 1){
            float4 t;
            t = __ldg((const float4*)(fw(0, ln)    + k4)); w0[0]=t.x; w0[1]=t.y; w0[2]=t.z; w0[3]=t.w;
            t = __ldg((const float4*)(fw(0, ln+32) + k4)); w1[0]=t.x; w1[1]=t.y; w1[2]=t.z; w1[3]=t.w;
        } else {
            const float *p0 = fw(0, ln), *p1 = fw(0, ln+32);
            #pragma unroll
            for (int i=0;i<4;i++){ w0[i]=__ldg(p0+(size_t)(k4+i)*LDW); w1[i]=__ldg(p1+(size_t)(k4+i)*LDW); }
        }
    }
    for (int c = 0; c < nch; ++c){
        xs[k4+0][ln]=x0.x; xs[k4+1][ln]=x0.y; xs[k4+2][ln]=x0.z; xs[k4+3][ln]=x0.w;
        xs[k4+0][ln+32]=x1.x; xs[k4+1][ln+32]=x1.y; xs[k4+2][ln+32]=x1.z; xs[k4+3][ln+32]=x1.w;
        ws[k4+0][ln]=w0[0]; ws[k4+1][ln]=w0[1]; ws[k4+2][ln]=w0[2]; ws[k4+3][ln]=w0[3];
        ws[k4+0][ln+32]=w1[0]; ws[k4+1][ln+32]=w1[1]; ws[k4+2][ln+32]=w1[2]; ws[k4+3][ln+32]=w1[3];
        __syncthreads();
        if (c+1 < nch){
            x0 = __ldcg((const float4*)(fx(c+1, ln)    + k4));
            x1 = __ldcg((const float4*)(fx(c+1, ln+32) + k4));
            if constexpr (LDW == 1){
                float4 t;
                t = __ldg((const float4*)(fw(c+1, ln)    + k4)); w0[0]=t.x; w0[1]=t.y; w0[2]=t.z; w0[3]=t.w;
                t = __ldg((const float4*)(fw(c+1, ln+32) + k4)); w1[0]=t.x; w1[1]=t.y; w1[2]=t.z; w1[3]=t.w;
            } else {
                const float *p0 = fw(c+1, ln), *p1 = fw(c+1, ln+32);
                #pragma unroll
                for (int i=0;i<4;i++){ w0[i]=__ldg(p0+(size_t)(k4+i)*LDW); w1[i]=__ldg(p1+(size_t)(k4+i)*LDW); }
            }
        }
        #pragma unroll 16
        for (int kk = 0; kk < 32; ++kk){
            float4 xv = *(const float4*)&xs[kk][tb4];
            float4 wv = *(const float4*)&ws[kk][tj4];
            a[0][0]=fmaf(xv.x,wv.x,a[0][0]); a[0][1]=fmaf(xv.x,wv.y,a[0][1]);
            a[0][2]=fmaf(xv.x,wv.z,a[0][2]); a[0][3]=fmaf(xv.x,wv.w,a[0][3]);
            a[1][0]=fmaf(xv.y,wv.x,a[1][0]); a[1][1]=fmaf(xv.y,wv.y,a[1][1]);
            a[1][2]=fmaf(xv.y,wv.z,a[1][2]); a[1][3]=fmaf(xv.y,wv.w,a[1][3]);
            a[2][0]=fmaf(xv.z,wv.x,a[2][0]); a[2][1]=fmaf(xv.z,wv.y,a[2][1]);
            a[2][2]=fmaf(xv.z,wv.z,a[2][2]); a[2][3]=fmaf(xv.z,wv.w,a[2][3]);
            a[3][0]=fmaf(xv.w,wv.x,a[3][0]); a[3][1]=fmaf(xv.w,wv.y,a[3][1]);
            a[3][2]=fmaf(xv.w,wv.z,a[3][2]); a[3][3]=fmaf(xv.w,wv.w,a[3][3]);
        }
        __syncthreads();
    }
}

// ---------------------------------------------------------------------------
__global__ __launch_bounds__(256, 1) void kMain(
    const int*   __restrict__ toks, const float* __restrict__ ctx,
    const float* __restrict__ h0i,  const float* __restrict__ c0i,
    const float* __restrict__ feedi,const float* __restrict__ emb,
    const float* __restrict__ Wih0, const float* __restrict__ Whh0,
    const float* __restrict__ bih0, const float* __restrict__ bhh0,
    const float* __restrict__ Wih1, const float* __restrict__ Whh1,
    const float* __restrict__ bih1, const float* __restrict__ bhh1,
    const float* __restrict__ Wa,   const float* __restrict__ Wout,
    float* __restrict__ dout)
{
    __shared__ __align__(16) float xs[32][68];
    __shared__ __align__(16) float ws[32][68];
    __shared__ float qs[512];
    __shared__ float sSc[64], sAl[64];

    const int blk = blockIdx.x, tid = threadIdx.x;
    const int tb4 = (tid >> 4) << 2;
    const int tj4 = (tid & 15) << 2;
    const int gid = blk*256 + tid;          // 0..32767 == b*512 + u
    const int gu  = gid & 511;

    // read barrier generation (safe: flag only changes after all CTAs arrive)
    unsigned bgen = *(volatile unsigned*)&g_bargen;

    // ---- init: state -> globals (cg), c-state -> registers, bias sums ----
    __stcg(&g_h0[0][gid], h0i[gid]);
    __stcg(&g_h1[0][gid], h0i[BH + gid]);
    __stcg(&g_feed[gid],  feedi[gid]);
    float c0reg = c0i[gid];
    float c1regA = 0.f, c1regB = 0.f;       // layer-1 c, owned by blocks 0..63
    if (blk < Bz){
        c1regA = c0i[BH + blk*Hd + tid];
        c1regB = c0i[BH + blk*Hd + tid + 256];
    }
    const float bs0i = __ldg(bih0+gu)      + __ldg(bhh0+gu);
    const float bs0f = __ldg(bih0+512+gu)  + __ldg(bhh0+512+gu);
    const float bs0g = __ldg(bih0+1024+gu) + __ldg(bhh0+1024+gu);
    const float bs0o = __ldg(bih0+1536+gu) + __ldg(bhh0+1536+gu);
    float bs1[8];   // layer-1 bias sums for u=tid and u=tid+256, 4 gates each
    #pragma unroll
    for (int g = 0; g < 4; ++g){
        bs1[g]   = __ldg(bih1+g*512+tid)     + __ldg(bhh1+g*512+tid);
        bs1[4+g] = __ldg(bih1+g*512+tid+256) + __ldg(bhh1+g*512+tid+256);
    }

    // ---- one-time ctxW = ctx @ Wa^T  (4096 x 512, K = 512) ----
    for (int it = 0; it < 4; ++it){
        int tile = it*NB + blk;             // 0..511
        int sb0 = (tile >> 3) << 6;
        int kc0 = (tile & 7) << 6;
        float a[4][4] = {};
        auto fx = [&](int c, int r) -> const float* {
            return ctx + (size_t)(sb0 + r)*Hd + (c<<5);
        };
        auto fw = [&](int c, int col) -> const float* {
            return Wa + (size_t)(c<<5)*Hd + kc0 + col;
        };
        tile_gemm44<Hd>(a, fx, fw, 16, xs, ws);
        #pragma unroll
        for (int bi = 0; bi < 4; ++bi){
            float4 v = make_float4(a[bi][0],a[bi][1],a[bi][2],a[bi][3]);
            *(float4*)&g_ctxW[(size_t)(sb0 + tb4 + bi)*Hd + kc0 + tj4] = v;
        }
    }
    gridbar_to(++bgen);

    // ---- time loop ----
    for (int t = 0; t < Tt; ++t){
        const int p = t & 1;
        const float* h0p = g_h0[p];
        const float* h1p = g_h1[p];
        float* h0n = g_h0[p^1];
        float* h1n = g_h1[p^1];

        // Phase A1: gates0 partials. 32 j-tiles x 4 K-splits (K=384).
        {
            const int ks = blk >> 5, j0 = (blk & 31) << 6;
            const int kbase = ks * 384;
            float a[4][4] = {};
            auto fx = [&](int c, int r) -> const float* {
                int kg = kbase + (c<<5);
                if (kg < 512)  return emb + (size_t)__ldg(toks + t*Bz + r)*512 + kg;
                if (kg < 1024) return (const float*)g_feed + (size_t)r*Hd + (kg - 512);
                return h0p + (size_t)r*Hd + (kg - 1024);
            };
            auto fw = [&](int c, int r) -> const float* {
                int kg = kbase + (c<<5);
                if (kg < 1024) return Wih0 + (size_t)(j0 + r)*1024 + kg;
                return Whh0 + (size_t)(j0 + r)*512 + (kg - 1024);
            };
            tile_gemm44<1>(a, fx, fw, 12, xs, ws);
            float* gp = g_g0[ks];
            #pragma unroll
            for (int bi = 0; bi < 4; ++bi){
                float4 v = make_float4(a[bi][0],a[bi][1],a[bi][2],a[bi][3]);
                __stcg((float4*)&gp[(size_t)(tb4 + bi)*2048 + j0 + tj4], v);
            }
        }
        gridbar_to(++bgen);

        // Phase A2: combine + LSTM cell 0 (c0 in registers)
        {
            float vi = bs0i, vf = bs0f, vg = bs0g, vo = bs0o;
            const int base = (gid >> 9) * 2048 + gu;
            #pragma unroll
            for (int ks = 0; ks < 4; ++ks){
                const float* G = g_g0[ks] + base;
                vi += __ldcg(G); vf += __ldcg(G+512); vg += __ldcg(G+1024); vo += __ldcg(G+1536);
            }
            float cn = sigf(vf)*c0reg + sigf(vi)*tanhf(vg);
            float hn = sigf(vo)*tanhf(cn);
            c0reg = cn;
            __stcg(&h0n[gid], hn);
            if (t == Tt-1){ dout[OFF_HF + gid] = hn; dout[OFF_CF + gid] = cn; }
        }
        gridbar_to(++bgen);

        // Phase B1: gates1 partials. 32 j-tiles x 4 K-splits (K=256).
        {
            const int ks = blk >> 5, j0 = (blk & 31) << 6;
            const int kbase = ks << 8;
            float a[4][4] = {};
            auto fx = [&](int c, int r) -> const float* {
                int kg = kbase + (c<<5);
                if (kg < 512) return (const float*)h0n + (size_t)r*Hd + kg;
                return h1p + (size_t)r*Hd + (kg - 512);
            };
            auto fw = [&](int c, int r) -> const float* {
                int kg = kbase + (c<<5);
                if (kg < 512) return Wih1 + (size_t)(j0 + r)*512 + kg;
                return Whh1 + (size_t)(j0 + r)*512 + (kg - 512);
            };
            tile_gemm44<1>(a, fx, fw, 8, xs, ws);
            float* gp = g_g1[ks];
            #pragma unroll
            for (int bi = 0; bi < 4; ++bi){
                float4 v = make_float4(a[bi][0],a[bi][1],a[bi][2],a[bi][3]);
                __stcg((float4*)&gp[(size_t)(tb4 + bi)*2048 + j0 + tj4], v);
            }
        }
        gridbar_to(++bgen);

        // Phase S (blocks 0..63): fused LSTM cell 1 + attention.
        if (blk < Bz){
            const int b = blk;
            // cell 1 for (b, tid) and (b, tid+256); h1n -> qs + global
            #pragma unroll
            for (int half = 0; half < 2; ++half){
                const int u = tid + half*256;
                float vi = bs1[half*4+0], vf = bs1[half*4+1], vg = bs1[half*4+2], vo = bs1[half*4+3];
                const int base = b*2048 + u;
                #pragma unroll
                for (int ks = 0; ks < 4; ++ks){
                    const float* G = g_g1[ks] + base;
                    vi += __ldcg(G); vf += __ldcg(G+512); vg += __ldcg(G+1024); vo += __ldcg(G+1536);
                }
                float cold = half ? c1regB : c1regA;
                float cn = sigf(vf)*cold + sigf(vi)*tanhf(vg);
                float hn = sigf(vo)*tanhf(cn);
                if (half) c1regB = cn; else c1regA = cn;
                qs[u] = hn;
                __stcg(&h1n[b*Hd + u], hn);
                if (t == Tt-1){ dout[OFF_HF + BH + b*Hd + u] = hn; dout[OFF_CF + BH + b*Hd + u] = cn; }
            }
            __syncthreads();
            // scores: warp w -> s = w*8..w*8+7, lanes over h (coalesced)
            const int wp = tid >> 5, lane = tid & 31;
            #pragma unroll
            for (int si = 0; si < 8; ++si){
                const int s = wp*8 + si;
                const float* cw = g_ctxW + ((size_t)(s*Bz + b) << 9) + lane;
                float acc = 0.f;
                #pragma unroll
                for (int i = 0; i < 16; ++i) acc = fmaf(qs[lane + (i<<5)], __ldg(cw + (i<<5)), acc);
                #pragma unroll
                for (int o = 16; o; o >>= 1) acc += __shfl_xor_sync(0xffffffffu, acc, o);
                if (lane == 0) sSc[s] = acc;
            }
            __syncthreads();
            // softmax over S=64 (warp 0)
            if (tid < 32){
                float v0 = sSc[tid], v1 = sSc[tid+32];
                float m = fmaxf(v0, v1);
                #pragma unroll
                for (int o = 16; o; o >>= 1) m = fmaxf(m, __shfl_xor_sync(0xffffffffu, m, o));
                float e0 = __expf(v0 - m), e1 = __expf(v1 - m);
                float ssum = e0 + e1;
                #pragma unroll
                for (int o = 16; o; o >>= 1) ssum += __shfl_xor_sync(0xffffffffu, ssum, o);
                float inv = 1.f/ssum;
                sAl[tid] = e0*inv;  sAl[tid+32] = e1*inv;
                dout[OFF_AT + t*Bz*Sl + b*Sl + tid]      = e0*inv;
                dout[OFF_AT + t*Bz*Sl + b*Sl + tid + 32] = e1*inv;
            }
            __syncthreads();
            // cvec[h] = sum_s al[s]*ctx[s,b,h]
            for (int h = tid; h < Hd; h += 256){
                float acc = 0.f;
                const float* cp = ctx + ((size_t)b << 9) + h;
                #pragma unroll 8
                for (int s2 = 0; s2 < Sl; ++s2) acc = fmaf(sAl[s2], __ldg(cp + ((size_t)s2 << 15)), acc);
                __stcg(&g_cvec[(b<<9) + h], acc);
            }
        }
        gridbar_to(++bgen);

        // Phase O1: Wout partials. 8 j-tiles x 16 K-splits (K=64).
        {
            const int ks = blk >> 3, j0 = (blk & 7) << 6;
            const int kbase = ks << 6;
            const float* xb   = (ks < 8) ? (const float*)g_cvec : (const float*)h1n;
            const int    koff = (ks < 8) ? kbase : (kbase - 512);
            float a[4][4] = {};
            auto fx = [&](int c, int r) -> const float* {
                return xb + (size_t)r*Hd + koff + (c<<5);
            };
            auto fw = [&](int c, int r) -> const float* {
                return Wout + (size_t)(j0 + r)*1024 + kbase + (c<<5);
            };
            tile_gemm44<1>(a, fx, fw, 2, xs, ws);
            float* gp = g_op[ks];
            #pragma unroll
            for (int bi = 0; bi < 4; ++bi){
                float4 v = make_float4(a[bi][0],a[bi][1],a[bi][2],a[bi][3]);
                __stcg((float4*)&gp[(size_t)(tb4 + bi)*Hd + j0 + tj4], v);
            }
        }
        gridbar_to(++bgen);

        // Phase O2: combine 16 partials + tanh -> feed, outputs[t], feedf
        {
            float s = 0.f;
            #pragma unroll
            for (int ks = 0; ks < 16; ++ks) s += __ldcg(&g_op[ks][gid]);
            float o = tanhf(s);
            __stcg(&g_feed[gid], o);
            dout[t*BH + gid] = o;
            if (t == Tt-1) dout[OFF_FF + gid] = o;
        }
        gridbar_to(++bgen);
    }
}

// ---------------------------------------------------------------------------
extern "C" void kernel_launch(void* const* d_in, const int* in_sizes, int n_in,
                              void* d_out, int out_size)
{
    const int*   toks = (const int*)  d_in[0];
    // d_in[1] = src (unused by the reference computation)
    const float* ctx  = (const float*)d_in[2];
    const float* h0   = (const float*)d_in[3];
    const float* c0   = (const float*)d_in[4];
    const float* feed = (const float*)d_in[5];
    const float* emb  = (const float*)d_in[6];
    const float* Wih0 = (const float*)d_in[7];
    const float* Whh0 = (const float*)d_in[8];
    const float* bih0 = (const float*)d_in[9];
    const float* bhh0 = (const float*)d_in[10];
    const float* Wih1 = (const float*)d_in[11];
    const float* Whh1 = (const float*)d_in[12];
    const float* bih1 = (const float*)d_in[13];
    const float* bhh1 = (const float*)d_in[14];
    const float* Wa   = (const float*)d_in[15];
    const float* Wout = (const float*)d_in[16];
    float* dout = (float*)d_out;

    kMain<<<NB, 256>>>(toks, ctx, h0, c0, feed, emb,
                       Wih0, Whh0, bih0, bhh0,
                       Wih1, Whh1, bih1, bhh1,
                       Wa, Wout, dout);
}

// round 10
// speedup vs baseline: 1.7319x; 1.7319x over previous
#include <cuda_runtime.h>
#include <math.h>

// Problem constants
#define Bz 64
#define Hd 512
#define Sl 64
#define Tt 32
#define BH (Bz*Hd)
#define NB 128
#define NT 512

// Output layout
#define OFF_AT 1048576
#define OFF_HF 1179648
#define OFF_CF 1245184
#define OFF_FF 1310720

// ---------------------------------------------------------------------------
// Persistent storage (no allocation allowed).
// Transposed weights [k][j] (written once, read via __ldg -> L1-resident):
__device__ float g_WT0[1536*2048];   // [emb|feed|h0] -> gates0
__device__ float g_WT1[1024*2048];   // [h0n|h1p]     -> gates1
__device__ float g_WoT[1024*512];    // [cvec|h1n]    -> out
__device__ float g_ctxT[512*4096];   // ctx transposed [h][sb]
__device__ float g_ctxW[4096*512];   // [sb][k] = sum_j ctx[sb][j] * Wa[j][k]
// Transposed activations [u][b] (cross-block: stcg/ldcg only):
__device__ float g_h0T[Hd*Bz], g_h1T[Hd*Bz], g_feedT[Hd*Bz], g_cvecT[Hd*Bz], g_embT[Hd*Bz];
// Split-K partials [j][b]:
__device__ float g_g0[8][2048*64];
__device__ float g_g1[8][2048*64];
__device__ float g_op[32][512*64];
__device__ unsigned g_barcnt = 0u;
__device__ unsigned g_bargen = 0u;

__device__ __forceinline__ float sigf(float x){ return 1.0f/(1.0f+__expf(-x)); }

// Grid barrier: acquire/release atomics only (no membar.gl -> no L1 flush).
__device__ __forceinline__ void gridbar_to(unsigned target){
    __syncthreads();
    if (threadIdx.x == 0){
        unsigned old;
        asm volatile("atom.acq_rel.gpu.global.add.u32 %0, [%1], 1;"
                     : "=r"(old) : "l"(&g_barcnt) : "memory");
        if (old == (unsigned)(NB-1)){
            g_barcnt = 0u;
            asm volatile("st.release.gpu.global.u32 [%0], %1;"
                         :: "l"(&g_bargen), "r"(target) : "memory");
        } else {
            unsigned g;
            do {
                asm volatile("ld.acquire.gpu.global.u32 %0, [%1];"
                             : "=r"(g) : "l"(&g_bargen) : "memory");
            } while (g != target);
        }
    }
    __syncthreads();
}

// ---------------------------------------------------------------------------
// 64b x 128j tile GEMM, 512 threads, 4b x 4j micro-tile (16 accums).
// Operands pre-transposed: x chunk rows [k][b] (pitch xpitch), w chunk rows
// [k][j] (pitch wpitch). Fully coalesced LDG, minimal-wavefront STS.128,
// double-buffered smem, ONE __syncthreads per chunk.
// ---------------------------------------------------------------------------
template<bool XCG, class FX, class FW>
__device__ __forceinline__ void gemm_tile(float (&a)[4][4], FX fx, FW fw,
        int nch, int xpitch, int wpitch, float* sx, float* sw)
{
    const int tid = threadIdx.x;
    const int bq = tid & 15, kx = tid >> 4;    // x loader: (k,b-quad)
    const int jq = tid & 31, kw = tid >> 5;    // w loader: (k,j-quad) x2
    const int tb4 = (tid & 15) << 2, tj4 = (tid >> 4) << 2;
    float4 xv, wv0, wv1;

    // stage chunk 0
    {
        const float* xp = fx(0) + kx*xpitch + (bq<<2);
        xv  = XCG ? __ldcg((const float4*)xp) : __ldg((const float4*)xp);
        const float* wp = fw(0);
        wv0 = __ldg((const float4*)(wp + (size_t)kw*wpitch + (jq<<2)));
        wv1 = __ldg((const float4*)(wp + (size_t)(kw+16)*wpitch + (jq<<2)));
        *(float4*)(sx + kx*68 + (bq<<2))        = xv;
        *(float4*)(sw + kw*132 + (jq<<2))       = wv0;
        *(float4*)(sw + (kw+16)*132 + (jq<<2))  = wv1;
    }
    __syncthreads();

    for (int c = 0; c < nch; ++c){
        const bool more = (c+1 < nch);
        if (more){
            const float* xp = fx(c+1) + kx*xpitch + (bq<<2);
            xv  = XCG ? __ldcg((const float4*)xp) : __ldg((const float4*)xp);
            const float* wp = fw(c+1);
            wv0 = __ldg((const float4*)(wp + (size_t)kw*wpitch + (jq<<2)));
            wv1 = __ldg((const float4*)(wp + (size_t)(kw+16)*wpitch + (jq<<2)));
        }
        const float* xb = sx + (c&1)*2176;
        const float* wb = sw + (c&1)*4224;
        #pragma unroll
        for (int kk = 0; kk < 32; ++kk){
            float4 x4 = *(const float4*)(xb + kk*68 + tb4);
            float4 w4 = *(const float4*)(wb + kk*132 + tj4);
            a[0][0]=fmaf(x4.x,w4.x,a[0][0]); a[0][1]=fmaf(x4.x,w4.y,a[0][1]);
            a[0][2]=fmaf(x4.x,w4.z,a[0][2]); a[0][3]=fmaf(x4.x,w4.w,a[0][3]);
            a[1][0]=fmaf(x4.y,w4.x,a[1][0]); a[1][1]=fmaf(x4.y,w4.y,a[1][1]);
            a[1][2]=fmaf(x4.y,w4.z,a[1][2]); a[1][3]=fmaf(x4.y,w4.w,a[1][3]);
            a[2][0]=fmaf(x4.z,w4.x,a[2][0]); a[2][1]=fmaf(x4.z,w4.y,a[2][1]);
            a[2][2]=fmaf(x4.z,w4.z,a[2][2]); a[2][3]=fmaf(x4.z,w4.w,a[2][3]);
            a[3][0]=fmaf(x4.w,w4.x,a[3][0]); a[3][1]=fmaf(x4.w,w4.y,a[3][1]);
            a[3][2]=fmaf(x4.w,w4.z,a[3][2]); a[3][3]=fmaf(x4.w,w4.w,a[3][3]);
        }
        if (more){
            float* xn = sx + ((c+1)&1)*2176;
            float* wn = sw + ((c+1)&1)*4224;
            *(float4*)(xn + kx*68 + (bq<<2))        = xv;
            *(float4*)(wn + kw*132 + (jq<<2))       = wv0;
            *(float4*)(wn + (kw+16)*132 + (jq<<2))  = wv1;
        }
        __syncthreads();
    }
}

// ---------------------------------------------------------------------------
__global__ __launch_bounds__(NT, 1) void kMain(
    const int*   __restrict__ toks, const float* __restrict__ ctx,
    const float* __restrict__ h0i,  const float* __restrict__ c0i,
    const float* __restrict__ feedi,const float* __restrict__ emb,
    const float* __restrict__ Wih0, const float* __restrict__ Whh0,
    const float* __restrict__ bih0, const float* __restrict__ bhh0,
    const float* __restrict__ Wih1, const float* __restrict__ Whh1,
    const float* __restrict__ bih1, const float* __restrict__ bhh1,
    const float* __restrict__ Wa,   const float* __restrict__ Wout,
    float* __restrict__ dout)
{
    extern __shared__ float smem[];
    float* sx  = smem;                    // 2 x 32 x 68  = 4352
    float* sw  = smem + 4352;             // 2 x 32 x 132 = 8448
    float* qs  = smem + 4352 + 8448;      // 512
    float* sSc = qs + 512;                // 64
    float* sAl = sSc + 64;                // 64

    const int blk = blockIdx.x, tid = threadIdx.x;
    const int tb4 = (tid & 15) << 2, tj4 = (tid >> 4) << 2;

    unsigned bgen = *(volatile unsigned*)&g_bargen;

    // ---- per-thread persistent state (owners) ----
    float c0reg = 0.f, bs0i=0.f, bs0f=0.f, bs0g=0.f, bs0o=0.f;
    if (tid < 256){
        int elem = blk*256 + tid;         // = u*64 + b
        int u = elem >> 6, b = elem & 63;
        c0reg = c0i[b*Hd + u];
        bs0i = __ldg(bih0+u)      + __ldg(bhh0+u);
        bs0f = __ldg(bih0+512+u)  + __ldg(bhh0+512+u);
        bs0g = __ldg(bih0+1024+u) + __ldg(bhh0+1024+u);
        bs0o = __ldg(bih0+1536+u) + __ldg(bhh0+1536+u);
    }
    float c1reg = 0.f, bs1[4] = {0.f,0.f,0.f,0.f};
    if (blk < Bz){
        c1reg = c0i[BH + blk*Hd + tid];
        #pragma unroll
        for (int g = 0; g < 4; ++g)
            bs1[g] = __ldg(bih1+g*512+tid) + __ldg(bhh1+g*512+tid);
    }

    // ---- init: transposed state + emb(t=0) ----
    if (tid < 256){
        int idx = blk*256 + tid;          // = b*512 + u (input layout)
        int b = idx >> 9, u = idx & 511;
        __stcg(&g_h0T[u*64+b],  h0i[idx]);
        __stcg(&g_h1T[u*64+b],  h0i[BH + idx]);
        __stcg(&g_feedT[u*64+b],feedi[idx]);
        __stcg(&g_embT[u*64+b], __ldg(emb + (size_t)__ldg(toks+b)*512 + u));
    }

    // ---- one-time transposes (weights, ctx) via smem 64x64 tiles ----
    // NOTE: Wa is NOT transposed — Wa[j][k] row-major is already the
    // [reduction j][output k] layout the ctxW GEMM needs.
    {
        float* ts = sx;                   // 64*65 = 4160 <= 4352
        for (int tl = blk; tl < 1920; tl += NB){
            const float* sp; float* dp;
            int spitch, sk0, srow0, dpitch, dk0, dj0;
            if (tl < 768){        // WT0 [1536][2048] <- Wih0[2048][1024], Whh0[2048][512]
                int kt=tl>>5, jt=tl&31; dk0=kt<<6; dj0=jt<<6; srow0=dj0;
                dp=g_WT0; dpitch=2048;
                if (dk0<1024){ sp=Wih0; spitch=1024; sk0=dk0; }
                else         { sp=Whh0; spitch=512;  sk0=dk0-1024; }
            } else if (tl < 1280){ // WT1 [1024][2048] <- Wih1/Whh1 [2048][512]
                int ti=tl-768; int kt=ti>>5, jt=ti&31; dk0=kt<<6; dj0=jt<<6; srow0=dj0;
                dp=g_WT1; dpitch=2048;
                if (dk0<512){ sp=Wih1; spitch=512; sk0=dk0; }
                else        { sp=Whh1; spitch=512; sk0=dk0-512; }
            } else if (tl < 1408){ // WoT [1024][512] <- Wout [512][1024]
                int ti=tl-1280; int kt=ti>>3, jt=ti&7; dk0=kt<<6; dj0=jt<<6; srow0=dj0;
                dp=g_WoT; dpitch=512; sp=Wout; spitch=1024; sk0=dk0;
            } else {               // ctxT [512][4096] <- ctx [4096][512]
                int ti=tl-1408; int kt=ti>>6, jt=ti&63; dk0=kt<<6; dj0=jt<<6; srow0=dj0;
                dp=g_ctxT; dpitch=4096; sp=ctx; spitch=512; sk0=dk0;
            }
            #pragma unroll
            for (int it2=0; it2<2; ++it2){
                int q = it2*512 + tid; int jr=q>>4, kc4=(q&15)<<2;
                float4 v = __ldg((const float4*)(sp + (size_t)(srow0+jr)*spitch + sk0 + kc4));
                ts[(kc4+0)*65+jr]=v.x; ts[(kc4+1)*65+jr]=v.y;
                ts[(kc4+2)*65+jr]=v.z; ts[(kc4+3)*65+jr]=v.w;
            }
            __syncthreads();
            #pragma unroll
            for (int it2=0; it2<2; ++it2){
                int q = it2*512 + tid; int kr=q>>4, jc4=(q&15)<<2;
                float4 v = make_float4(ts[kr*65+jc4], ts[kr*65+jc4+1],
                                       ts[kr*65+jc4+2], ts[kr*65+jc4+3]);
                *(float4*)(dp + (size_t)(dk0+kr)*dpitch + dj0 + jc4) = v;
            }
            __syncthreads();
        }
    }
    gridbar_to(++bgen);

    // ---- one-time ctxW[sb][k] = sum_j ctx[sb][j] * Wa[j][k] ----
    for (int it = 0; it < 2; ++it){
        int job = it*NB + blk;            // 256 jobs: 64 row-tiles x 4 k-tiles
        int sb0 = (job >> 2) << 6;
        int j0v = (job & 3) << 7;
        float a[4][4] = {};
        auto fx = [&](int c) -> const float* { return g_ctxT + (size_t)(c<<5)*4096 + sb0; };
        auto fw = [&](int c) -> const float* { return Wa + (size_t)(c<<5)*512 + j0v; };
        gemm_tile<false>(a, fx, fw, 16, 4096, 512, sx, sw);
        #pragma unroll
        for (int bi = 0; bi < 4; ++bi)
            *(float4*)&g_ctxW[(size_t)(sb0 + tb4 + bi)*512 + j0v + tj4]
                = make_float4(a[bi][0],a[bi][1],a[bi][2],a[bi][3]);
    }
    gridbar_to(++bgen);

    // ---- time loop ----
    for (int t = 0; t < Tt; ++t){

        // Phase A1: gates0 partials. 16 j-tiles(128) x 8 K-splits (K=192).
        {
            const int ks = blk >> 4, j0v = (blk & 15) << 7;
            const int kbase = ks * 192;
            float a[4][4] = {};
            auto fx = [&](int c) -> const float* {
                int kg = kbase + (c<<5);
                if (kg < 512)  return g_embT + kg*64;
                if (kg < 1024) return g_feedT + (kg-512)*64;
                return g_h0T + (kg-1024)*64;
            };
            auto fw = [&](int c) -> const float* {
                return g_WT0 + (size_t)(kbase + (c<<5))*2048 + j0v;
            };
            gemm_tile<true>(a, fx, fw, 6, 64, 2048, sx, sw);
            float* gp = g_g0[ks];
            #pragma unroll
            for (int jj = 0; jj < 4; ++jj)
                __stcg((float4*)&gp[(j0v + tj4 + jj)*64 + tb4],
                       make_float4(a[0][jj],a[1][jj],a[2][jj],a[3][jj]));
        }
        gridbar_to(++bgen);

        // Phase A2: combine + LSTM cell 0 (coalesced: elem = u*64+b)
        if (tid < 256){
            int elem = blk*256 + tid;
            int u = elem >> 6, b = elem & 63;
            float vi=bs0i, vf=bs0f, vg=bs0g, vo=bs0o;
            #pragma unroll
            for (int ks = 0; ks < 8; ++ks){
                const float* G = g_g0[ks];
                vi += __ldcg(&G[(u       )*64 + b]);
                vf += __ldcg(&G[(512+u)  *64 + b]);
                vg += __ldcg(&G[(1024+u) *64 + b]);
                vo += __ldcg(&G[(1536+u) *64 + b]);
            }
            float cn = sigf(vf)*c0reg + sigf(vi)*tanhf(vg);
            float hn = sigf(vo)*tanhf(cn);
            c0reg = cn;
            __stcg(&g_h0T[elem], hn);
            if (t == Tt-1){ dout[OFF_HF + b*Hd + u] = hn; dout[OFF_CF + b*Hd + u] = cn; }
        }
        gridbar_to(++bgen);

        // Phase B1: gates1 partials. 16 j-tiles x 8 K-splits (K=128).
        {
            const int ks = blk >> 4, j0v = (blk & 15) << 7;
            const int kbase = ks << 7;
            float a[4][4] = {};
            auto fx = [&](int c) -> const float* {
                int kg = kbase + (c<<5);
                return (kg < 512) ? g_h0T + kg*64 : g_h1T + (kg-512)*64;
            };
            auto fw = [&](int c) -> const float* {
                return g_WT1 + (size_t)(kbase + (c<<5))*2048 + j0v;
            };
            gemm_tile<true>(a, fx, fw, 4, 64, 2048, sx, sw);
            float* gp = g_g1[ks];
            #pragma unroll
            for (int jj = 0; jj < 4; ++jj)
                __stcg((float4*)&gp[(j0v + tj4 + jj)*64 + tb4],
                       make_float4(a[0][jj],a[1][jj],a[2][jj],a[3][jj]));
        }
        gridbar_to(++bgen);

        // Phase S (blocks 0..63): cell 1 + scores + softmax + cvec.
        if (blk < Bz){
            const int b = blk, u = tid;
            float vi=bs1[0], vf=bs1[1], vg=bs1[2], vo=bs1[3];
            #pragma unroll
            for (int ks = 0; ks < 8; ++ks){
                const float* G = g_g1[ks];
                vi += __ldcg(&G[(u       )*64 + b]);
                vf += __ldcg(&G[(512+u)  *64 + b]);
                vg += __ldcg(&G[(1024+u) *64 + b]);
                vo += __ldcg(&G[(1536+u) *64 + b]);
            }
            float cn = sigf(vf)*c1reg + sigf(vi)*tanhf(vg);
            float hn = sigf(vo)*tanhf(cn);
            c1reg = cn;
            qs[u] = hn;
            __stcg(&g_h1T[u*64 + b], hn);
            if (t == Tt-1){ dout[OFF_HF + BH + b*Hd + u] = hn; dout[OFF_CF + BH + b*Hd + u] = cn; }
            __syncthreads();
            // scores: warp wp -> s = wp*4..+3, lanes over k (coalesced)
            const int wp = tid >> 5, lane = tid & 31;
            #pragma unroll
            for (int si = 0; si < 4; ++si){
                const int s = wp*4 + si;
                const float* cw = g_ctxW + ((size_t)(s*Bz + b) << 9) + lane;
                float acc = 0.f;
                #pragma unroll
                for (int i = 0; i < 16; ++i) acc = fmaf(qs[lane + (i<<5)], __ldg(cw + (i<<5)), acc);
                #pragma unroll
                for (int o = 16; o; o >>= 1) acc += __shfl_xor_sync(0xffffffffu, acc, o);
                if (lane == 0) sSc[s] = acc;
            }
            __syncthreads();
            if (tid < 32){
                float v0 = sSc[tid], v1 = sSc[tid+32];
                float m = fmaxf(v0, v1);
                #pragma unroll
                for (int o = 16; o; o >>= 1) m = fmaxf(m, __shfl_xor_sync(0xffffffffu, m, o));
                float e0 = __expf(v0 - m), e1 = __expf(v1 - m);
                float ssum = e0 + e1;
                #pragma unroll
                for (int o = 16; o; o >>= 1) ssum += __shfl_xor_sync(0xffffffffu, ssum, o);
                float inv = 1.f/ssum;
                sAl[tid] = e0*inv;  sAl[tid+32] = e1*inv;
                dout[OFF_AT + t*Bz*Sl + b*Sl + tid]      = e0*inv;
                dout[OFF_AT + t*Bz*Sl + b*Sl + tid + 32] = e1*inv;
            }
            __syncthreads();
            {   // cvec[h] for h = tid (coalesced ctx reads)
                float acc = 0.f;
                const float* cp = ctx + ((size_t)b << 9) + tid;
                #pragma unroll 8
                for (int s2 = 0; s2 < Sl; ++s2) acc = fmaf(sAl[s2], __ldg(cp + ((size_t)s2 << 15)), acc);
                __stcg(&g_cvecT[tid*64 + b], acc);
            }
        }
        gridbar_to(++bgen);

        // Phase O1: Wout partials. 4 j-tiles(128) x 32 K-splits (K=32, 1 chunk).
        {
            const int ks = blk >> 2, j0v = (blk & 3) << 7;
            const int kbase = ks << 5;
            float a[4][4] = {};
            auto fx = [&](int) -> const float* {
                return (ks < 16) ? g_cvecT + kbase*64 : g_h1T + (kbase-512)*64;
            };
            auto fw = [&](int) -> const float* {
                return g_WoT + (size_t)kbase*512 + j0v;
            };
            gemm_tile<true>(a, fx, fw, 1, 64, 512, sx, sw);
            float* gp = g_op[ks];
            #pragma unroll
            for (int jj = 0; jj < 4; ++jj)
                __stcg((float4*)&gp[(j0v + tj4 + jj)*64 + tb4],
                       make_float4(a[0][jj],a[1][jj],a[2][jj],a[3][jj]));
        }
        gridbar_to(++bgen);

        // Phase O2: combine 32 partials + tanh -> feedT, outputs[t], feedf;
        // also gather emb for step t+1 (transposed).
        if (tid < 256){
            int elem = blk*256 + tid;     // = h*64 + b
            int h = elem >> 6, b = elem & 63;
            float s = 0.f;
            #pragma unroll
            for (int ks = 0; ks < 32; ++ks) s += __ldcg(&g_op[ks][elem]);
            float o = tanhf(s);
            __stcg(&g_feedT[elem], o);
            dout[t*BH + b*Hd + h] = o;
            if (t == Tt-1) dout[OFF_FF + b*Hd + h] = o;
            if (t+1 < Tt){
                int b2 = elem >> 9, k2 = elem & 511;   // = b*512 + u view
                float ev = __ldg(emb + (size_t)__ldg(toks + (t+1)*Bz + b2)*512 + k2);
                __stcg(&g_embT[k2*64 + b2], ev);
            }
        }
        gridbar_to(++bgen);
    }
}

// ---------------------------------------------------------------------------
extern "C" void kernel_launch(void* const* d_in, const int* in_sizes, int n_in,
                              void* d_out, int out_size)
{
    const int*   toks = (const int*)  d_in[0];
    // d_in[1] = src (unused by the reference computation)
    const float* ctx  = (const float*)d_in[2];
    const float* h0   = (const float*)d_in[3];
    const float* c0   = (const float*)d_in[4];
    const float* feed = (const float*)d_in[5];
    const float* emb  = (const float*)d_in[6];
    const float* Wih0 = (const float*)d_in[7];
    const float* Whh0 = (const float*)d_in[8];
    const float* bih0 = (const float*)d_in[9];
    const float* bhh0 = (const float*)d_in[10];
    const float* Wih1 = (const float*)d_in[11];
    const float* Whh1 = (const float*)d_in[12];
    const float* bih1 = (const float*)d_in[13];
    const float* bhh1 = (const float*)d_in[14];
    const float* Wa   = (const float*)d_in[15];
    const float* Wout = (const float*)d_in[16];
    float* dout = (float*)d_out;

    const int shmem = 13440 * 4;   // 53.76 KB dynamic
    static int attr_set = 0;
    if (!attr_set){
        cudaFuncSetAttribute(kMain, cudaFuncAttributeMaxDynamicSharedMemorySize, shmem);
        attr_set = 1;
    }
    kMain<<<NB, NT, shmem>>>(toks, ctx, h0, c0, feed, emb,
                             Wih0, Whh0, bih0, bhh0,
                             Wih1, Whh1, bih1, bhh1,
                             Wa, Wout, dout);
}

// round 12
// speedup vs baseline: 1.7428x; 1.0063x over previous
#include <cuda_runtime.h>
#include <math.h>

// Problem constants
#define Bz 64
#define Hd 512
#define Sl 64
#define Tt 32
#define BH (Bz*Hd)
#define NB 128
#define NT 512

// Output layout
#define OFF_AT 1048576
#define OFF_HF 1179648
#define OFF_CF 1245184
#define OFF_FF 1310720

// ---------------------------------------------------------------------------
// Persistent storage (no allocation allowed).
// Transposed weights [k][j] (written once, read via __ldg -> L1-resident):
__device__ float g_WT0[1536*2048];   // [emb|feed|h0] -> gates0
__device__ float g_WT1[1024*2048];   // [h0n|h1p]     -> gates1
__device__ float g_WoT[1024*512];    // [cvec|h1n]    -> out
__device__ float g_ctxT[512*4096];   // ctx transposed [h][sb]
__device__ float g_ctxW[4096*512];   // [sb][k] = sum_j ctx[sb][j] * Wa[j][k]
// Transposed activations [u][b] (cross-block: stcg/ldcg only):
__device__ float g_h0T[Hd*Bz], g_h1T[Hd*Bz], g_feedT[Hd*Bz], g_cvecT[Hd*Bz], g_embT[Hd*Bz];
// Split-K partials [j][b]:
__device__ float g_g0[8][2048*64];
__device__ float g_g1[8][2048*64];
__device__ float g_op[32][512*64];
__device__ unsigned g_barcnt = 0u;
__device__ unsigned g_bargen = 0u;

__device__ __forceinline__ float sigf(float x){ return 1.0f/(1.0f+__expf(-x)); }

// Grid barrier: acquire/release atomics only (no membar.gl -> no L1 flush).
__device__ __forceinline__ void gridbar_to(unsigned target){
    __syncthreads();
    if (threadIdx.x == 0){
        unsigned old;
        asm volatile("atom.acq_rel.gpu.global.add.u32 %0, [%1], 1;"
                     : "=r"(old) : "l"(&g_barcnt) : "memory");
        if (old == (unsigned)(NB-1)){
            g_barcnt = 0u;
            asm volatile("st.release.gpu.global.u32 [%0], %1;"
                         :: "l"(&g_bargen), "r"(target) : "memory");
        } else {
            unsigned g;
            do {
                asm volatile("ld.acquire.gpu.global.u32 %0, [%1];"
                             : "=r"(g) : "l"(&g_bargen) : "memory");
            } while (g != target);
        }
    }
    __syncthreads();
}

// ---------------------------------------------------------------------------
// 64b x 128j tile GEMM, 512 threads, 4b x 4j micro-tile (16 accums).
// Operands pre-transposed: x chunk rows [k][b] (pitch xpitch), w chunk rows
// [k][j] (pitch wpitch). Fully coalesced LDG, minimal-wavefront STS.128,
// double-buffered smem, ONE __syncthreads per chunk.
// ---------------------------------------------------------------------------
template<bool XCG, class FX, class FW>
__device__ __forceinline__ void gemm_tile(float (&a)[4][4], FX fx, FW fw,
        int nch, int xpitch, int wpitch, float* sx, float* sw)
{
    const int tid = threadIdx.x;
    const int bq = tid & 15, kx = tid >> 4;    // x loader: (k,b-quad)
    const int jq = tid & 31, kw = tid >> 5;    // w loader: (k,j-quad) x2
    const int tb4 = (tid & 15) << 2, tj4 = (tid >> 4) << 2;
    float4 xv, wv0, wv1;

    // stage chunk 0
    {
        const float* xp = fx(0) + kx*xpitch + (bq<<2);
        xv  = XCG ? __ldcg((const float4*)xp) : __ldg((const float4*)xp);
        const float* wp = fw(0);
        wv0 = __ldg((const float4*)(wp + (size_t)kw*wpitch + (jq<<2)));
        wv1 = __ldg((const float4*)(wp + (size_t)(kw+16)*wpitch + (jq<<2)));
        *(float4*)(sx + kx*68 + (bq<<2))        = xv;
        *(float4*)(sw + kw*132 + (jq<<2))       = wv0;
        *(float4*)(sw + (kw+16)*132 + (jq<<2))  = wv1;
    }
    __syncthreads();

    for (int c = 0; c < nch; ++c){
        const bool more = (c+1 < nch);
        if (more){
            const float* xp = fx(c+1) + kx*xpitch + (bq<<2);
            xv  = XCG ? __ldcg((const float4*)xp) : __ldg((const float4*)xp);
            const float* wp = fw(c+1);
            wv0 = __ldg((const float4*)(wp + (size_t)kw*wpitch + (jq<<2)));
            wv1 = __ldg((const float4*)(wp + (size_t)(kw+16)*wpitch + (jq<<2)));
        }
        const float* xb = sx + (c&1)*2176;
        const float* wb = sw + (c&1)*4224;
        #pragma unroll
        for (int kk = 0; kk < 32; ++kk){
            float4 x4 = *(const float4*)(xb + kk*68 + tb4);
            float4 w4 = *(const float4*)(wb + kk*132 + tj4);
            a[0][0]=fmaf(x4.x,w4.x,a[0][0]); a[0][1]=fmaf(x4.x,w4.y,a[0][1]);
            a[0][2]=fmaf(x4.x,w4.z,a[0][2]); a[0][3]=fmaf(x4.x,w4.w,a[0][3]);
            a[1][0]=fmaf(x4.y,w4.x,a[1][0]); a[1][1]=fmaf(x4.y,w4.y,a[1][1]);
            a[1][2]=fmaf(x4.y,w4.z,a[1][2]); a[1][3]=fmaf(x4.y,w4.w,a[1][3]);
            a[2][0]=fmaf(x4.z,w4.x,a[2][0]); a[2][1]=fmaf(x4.z,w4.y,a[2][1]);
            a[2][2]=fmaf(x4.z,w4.z,a[2][2]); a[2][3]=fmaf(x4.z,w4.w,a[2][3]);
            a[3][0]=fmaf(x4.w,w4.x,a[3][0]); a[3][1]=fmaf(x4.w,w4.y,a[3][1]);
            a[3][2]=fmaf(x4.w,w4.z,a[3][2]); a[3][3]=fmaf(x4.w,w4.w,a[3][3]);
        }
        if (more){
            float* xn = sx + ((c+1)&1)*2176;
            float* wn = sw + ((c+1)&1)*4224;
            *(float4*)(xn + kx*68 + (bq<<2))        = xv;
            *(float4*)(wn + kw*132 + (jq<<2))       = wv0;
            *(float4*)(wn + (kw+16)*132 + (jq<<2))  = wv1;
        }
        __syncthreads();
    }
}

// ---------------------------------------------------------------------------
__global__ __launch_bounds__(NT, 1) void kMain(
    const int*   __restrict__ toks, const float* __restrict__ ctx,
    const float* __restrict__ h0i,  const float* __restrict__ c0i,
    const float* __restrict__ feedi,const float* __restrict__ emb,
    const float* __restrict__ Wih0, const float* __restrict__ Whh0,
    const float* __restrict__ bih0, const float* __restrict__ bhh0,
    const float* __restrict__ Wih1, const float* __restrict__ Whh1,
    const float* __restrict__ bih1, const float* __restrict__ bhh1,
    const float* __restrict__ Wa,   const float* __restrict__ Wout,
    float* __restrict__ dout)
{
    extern __shared__ float smem[];
    float* sx  = smem;                    // 2 x 32 x 68  = 4352
    float* sw  = smem + 4352;             // 2 x 32 x 132 = 8448
    float* qs  = smem + 4352 + 8448;      // 512
    float* sSc = qs + 512;                // 64
    float* sAl = sSc + 64;                // 64

    const int blk = blockIdx.x, tid = threadIdx.x;
    const int tb4 = (tid & 15) << 2, tj4 = (tid >> 4) << 2;

    unsigned bgen = *(volatile unsigned*)&g_bargen;

    // ---- per-thread persistent state (owners) ----
    float c0reg = 0.f, bs0i=0.f, bs0f=0.f, bs0g=0.f, bs0o=0.f;
    if (tid < 256){
        int elem = blk*256 + tid;         // = u*64 + b
        int u = elem >> 6, b = elem & 63;
        c0reg = c0i[b*Hd + u];
        bs0i = __ldg(bih0+u)      + __ldg(bhh0+u);
        bs0f = __ldg(bih0+512+u)  + __ldg(bhh0+512+u);
        bs0g = __ldg(bih0+1024+u) + __ldg(bhh0+1024+u);
        bs0o = __ldg(bih0+1536+u) + __ldg(bhh0+1536+u);
    }
    float c1reg = 0.f, bs1[4] = {0.f,0.f,0.f,0.f};
    if (blk < Bz){
        c1reg = c0i[BH + blk*Hd + tid];
        #pragma unroll
        for (int g = 0; g < 4; ++g)
            bs1[g] = __ldg(bih1+g*512+tid) + __ldg(bhh1+g*512+tid);
    }

    // ---- init: transposed state + emb(t=0) ----
    if (tid < 256){
        int idx = blk*256 + tid;          // = b*512 + u (input layout)
        int b = idx >> 9, u = idx & 511;
        __stcg(&g_h0T[u*64+b],  h0i[idx]);
        __stcg(&g_h1T[u*64+b],  h0i[BH + idx]);
        __stcg(&g_feedT[u*64+b],feedi[idx]);
        __stcg(&g_embT[u*64+b], __ldg(emb + (size_t)__ldg(toks+b)*512 + u));
    }

    // ---- one-time transposes (weights, ctx) via smem 64x64 tiles ----
    // NOTE: Wa is NOT transposed — Wa[j][k] row-major is already the
    // [reduction j][output k] layout the ctxW GEMM needs.
    {
        float* ts = sx;                   // 64*65 = 4160 <= 4352
        for (int tl = blk; tl < 1920; tl += NB){
            const float* sp; float* dp;
            int spitch, sk0, srow0, dpitch, dk0, dj0;
            if (tl < 768){        // WT0 [1536][2048] <- Wih0[2048][1024], Whh0[2048][512]
                int kt=tl>>5, jt=tl&31; dk0=kt<<6; dj0=jt<<6; srow0=dj0;
                dp=g_WT0; dpitch=2048;
                if (dk0<1024){ sp=Wih0; spitch=1024; sk0=dk0; }
                else         { sp=Whh0; spitch=512;  sk0=dk0-1024; }
            } else if (tl < 1280){ // WT1 [1024][2048] <- Wih1/Whh1 [2048][512]
                int ti=tl-768; int kt=ti>>5, jt=ti&31; dk0=kt<<6; dj0=jt<<6; srow0=dj0;
                dp=g_WT1; dpitch=2048;
                if (dk0<512){ sp=Wih1; spitch=512; sk0=dk0; }
                else        { sp=Whh1; spitch=512; sk0=dk0-512; }
            } else if (tl < 1408){ // WoT [1024][512] <- Wout [512][1024]
                int ti=tl-1280; int kt=ti>>3, jt=ti&7; dk0=kt<<6; dj0=jt<<6; srow0=dj0;
                dp=g_WoT; dpitch=512; sp=Wout; spitch=1024; sk0=dk0;
            } else {               // ctxT [512][4096] <- ctx [4096][512]
                int ti=tl-1408; int kt=ti>>6, jt=ti&63; dk0=kt<<6; dj0=jt<<6; srow0=dj0;
                dp=g_ctxT; dpitch=4096; sp=ctx; spitch=512; sk0=dk0;
            }
            #pragma unroll
            for (int it2=0; it2<2; ++it2){
                int q = it2*512 + tid; int jr=q>>4, kc4=(q&15)<<2;
                float4 v = __ldg((const float4*)(sp + (size_t)(srow0+jr)*spitch + sk0 + kc4));
                ts[(kc4+0)*65+jr]=v.x; ts[(kc4+1)*65+jr]=v.y;
                ts[(kc4+2)*65+jr]=v.z; ts[(kc4+3)*65+jr]=v.w;
            }
            __syncthreads();
            #pragma unroll
            for (int it2=0; it2<2; ++it2){
                int q = it2*512 + tid; int kr=q>>4, jc4=(q&15)<<2;
                float4 v = make_float4(ts[kr*65+jc4], ts[kr*65+jc4+1],
                                       ts[kr*65+jc4+2], ts[kr*65+jc4+3]);
                *(float4*)(dp + (size_t)(dk0+kr)*dpitch + dj0 + jc4) = v;
            }
            __syncthreads();
        }
    }
    gridbar_to(++bgen);

    // ---- one-time ctxW[sb][k] = sum_j ctx[sb][j] * Wa[j][k] ----
    for (int it = 0; it < 2; ++it){
        int job = it*NB + blk;            // 256 jobs: 64 row-tiles x 4 k-tiles
        int sb0 = (job >> 2) << 6;
        int j0v = (job & 3) << 7;
        float a[4][4] = {};
        auto fx = [&](int c) -> const float* { return g_ctxT + (size_t)(c<<5)*4096 + sb0; };
        auto fw = [&](int c) -> const float* { return Wa + (size_t)(c<<5)*512 + j0v; };
        gemm_tile<false>(a, fx, fw, 16, 4096, 512, sx, sw);
        #pragma unroll
        for (int bi = 0; bi < 4; ++bi)
            *(float4*)&g_ctxW[(size_t)(sb0 + tb4 + bi)*512 + j0v + tj4]
                = make_float4(a[bi][0],a[bi][1],a[bi][2],a[bi][3]);
    }
    gridbar_to(++bgen);

    // ---- time loop ----
    for (int t = 0; t < Tt; ++t){

        // Phase A1: gates0 partials. 16 j-tiles(128) x 8 K-splits (K=192).
        {
            const int ks = blk >> 4, j0v = (blk & 15) << 7;
            const int kbase = ks * 192;
            float a[4][4] = {};
            auto fx = [&](int c) -> const float* {
                int kg = kbase + (c<<5);
                if (kg < 512)  return g_embT + kg*64;
                if (kg < 1024) return g_feedT + (kg-512)*64;
                return g_h0T + (kg-1024)*64;
            };
            auto fw = [&](int c) -> const float* {
                return g_WT0 + (size_t)(kbase + (c<<5))*2048 + j0v;
            };
            gemm_tile<true>(a, fx, fw, 6, 64, 2048, sx, sw);
            float* gp = g_g0[ks];
            #pragma unroll
            for (int jj = 0; jj < 4; ++jj)
                __stcg((float4*)&gp[(j0v + tj4 + jj)*64 + tb4],
                       make_float4(a[0][jj],a[1][jj],a[2][jj],a[3][jj]));
        }
        gridbar_to(++bgen);

        // Phase A2: combine + LSTM cell 0 (coalesced: elem = u*64+b)
        if (tid < 256){
            int elem = blk*256 + tid;
            int u = elem >> 6, b = elem & 63;
            float vi=bs0i, vf=bs0f, vg=bs0g, vo=bs0o;
            #pragma unroll
            for (int ks = 0; ks < 8; ++ks){
                const float* G = g_g0[ks];
                vi += __ldcg(&G[(u       )*64 + b]);
                vf += __ldcg(&G[(512+u)  *64 + b]);
                vg += __ldcg(&G[(1024+u) *64 + b]);
                vo += __ldcg(&G[(1536+u) *64 + b]);
            }
            float cn = sigf(vf)*c0reg + sigf(vi)*tanhf(vg);
            float hn = sigf(vo)*tanhf(cn);
            c0reg = cn;
            __stcg(&g_h0T[elem], hn);
            if (t == Tt-1){ dout[OFF_HF + b*Hd + u] = hn; dout[OFF_CF + b*Hd + u] = cn; }
        }
        gridbar_to(++bgen);

        // Phase B1: gates1 partials. 16 j-tiles x 8 K-splits (K=128).
        {
            const int ks = blk >> 4, j0v = (blk & 15) << 7;
            const int kbase = ks << 7;
            float a[4][4] = {};
            auto fx = [&](int c) -> const float* {
                int kg = kbase + (c<<5);
                return (kg < 512) ? g_h0T + kg*64 : g_h1T + (kg-512)*64;
            };
            auto fw = [&](int c) -> const float* {
                return g_WT1 + (size_t)(kbase + (c<<5))*2048 + j0v;
            };
            gemm_tile<true>(a, fx, fw, 4, 64, 2048, sx, sw);
            float* gp = g_g1[ks];
            #pragma unroll
            for (int jj = 0; jj < 4; ++jj)
                __stcg((float4*)&gp[(j0v + tj4 + jj)*64 + tb4],
                       make_float4(a[0][jj],a[1][jj],a[2][jj],a[3][jj]));
        }
        gridbar_to(++bgen);

        // Phase S (blocks 0..63): cell 1 + scores + softmax + cvec.
        if (blk < Bz){
            const int b = blk, u = tid;
            float vi=bs1[0], vf=bs1[1], vg=bs1[2], vo=bs1[3];
            #pragma unroll
            for (int ks = 0; ks < 8; ++ks){
                const float* G = g_g1[ks];
                vi += __ldcg(&G[(u       )*64 + b]);
                vf += __ldcg(&G[(512+u)  *64 + b]);
                vg += __ldcg(&G[(1024+u) *64 + b]);
                vo += __ldcg(&G[(1536+u) *64 + b]);
            }
            float cn = sigf(vf)*c1reg + sigf(vi)*tanhf(vg);
            float hn = sigf(vo)*tanhf(cn);
            c1reg = cn;
            qs[u] = hn;
            __stcg(&g_h1T[u*64 + b], hn);
            if (t == Tt-1){ dout[OFF_HF + BH + b*Hd + u] = hn; dout[OFF_CF + BH + b*Hd + u] = cn; }
            __syncthreads();
            // scores: warp wp -> s = wp*4..+3, lanes over k (coalesced)
            const int wp = tid >> 5, lane = tid & 31;
            #pragma unroll
            for (int si = 0; si < 4; ++si){
                const int s = wp*4 + si;
                const float* cw = g_ctxW + ((size_t)(s*Bz + b) << 9) + lane;
                float acc = 0.f;
                #pragma unroll
                for (int i = 0; i < 16; ++i) acc = fmaf(qs[lane + (i<<5)], __ldg(cw + (i<<5)), acc);
                #pragma unroll
                for (int o = 16; o; o >>= 1) acc += __shfl_xor_sync(0xffffffffu, acc, o);
                if (lane == 0) sSc[s] = acc;
            }
            __syncthreads();
            if (tid < 32){
                float v0 = sSc[tid], v1 = sSc[tid+32];
                float m = fmaxf(v0, v1);
                #pragma unroll
                for (int o = 16; o; o >>= 1) m = fmaxf(m, __shfl_xor_sync(0xffffffffu, m, o));
                float e0 = __expf(v0 - m), e1 = __expf(v1 - m);
                float ssum = e0 + e1;
                #pragma unroll
                for (int o = 16; o; o >>= 1) ssum += __shfl_xor_sync(0xffffffffu, ssum, o);
                float inv = 1.f/ssum;
                sAl[tid] = e0*inv;  sAl[tid+32] = e1*inv;
                dout[OFF_AT + t*Bz*Sl + b*Sl + tid]      = e0*inv;
                dout[OFF_AT + t*Bz*Sl + b*Sl + tid + 32] = e1*inv;
            }
            __syncthreads();
            {   // cvec[h] for h = tid (coalesced ctx reads)
                float acc = 0.f;
                const float* cp = ctx + ((size_t)b << 9) + tid;
                #pragma unroll 8
                for (int s2 = 0; s2 < Sl; ++s2) acc = fmaf(sAl[s2], __ldg(cp + ((size_t)s2 << 15)), acc);
                __stcg(&g_cvecT[tid*64 + b], acc);
            }
        }
        gridbar_to(++bgen);

        // Phase O1: Wout partials. 4 j-tiles(128) x 32 K-splits (K=32, 1 chunk).
        {
            const int ks = blk >> 2, j0v = (blk & 3) << 7;
            const int kbase = ks << 5;
            float a[4][4] = {};
            auto fx = [&](int) -> const float* {
                return (ks < 16) ? g_cvecT + kbase*64 : g_h1T + (kbase-512)*64;
            };
            auto fw = [&](int) -> const float* {
                return g_WoT + (size_t)kbase*512 + j0v;
            };
            gemm_tile<true>(a, fx, fw, 1, 64, 512, sx, sw);
            float* gp = g_op[ks];
            #pragma unroll
            for (int jj = 0; jj < 4; ++jj)
                __stcg((float4*)&gp[(j0v + tj4 + jj)*64 + tb4],
                       make_float4(a[0][jj],a[1][jj],a[2][jj],a[3][jj]));
        }
        gridbar_to(++bgen);

        // Phase O2: combine 32 partials + tanh -> feedT, outputs[t], feedf;
        // also gather emb for step t+1 (transposed).
        if (tid < 256){
            int elem = blk*256 + tid;     // = h*64 + b
            int h = elem >> 6, b = elem & 63;
            float s = 0.f;
            #pragma unroll
            for (int ks = 0; ks < 32; ++ks) s += __ldcg(&g_op[ks][elem]);
            float o = tanhf(s);
            __stcg(&g_feedT[elem], o);
            dout[t*BH + b*Hd + h] = o;
            if (t == Tt-1) dout[OFF_FF + b*Hd + h] = o;
            if (t+1 < Tt){
                int b2 = elem >> 9, k2 = elem & 511;   // = b*512 + u view
                float ev = __ldg(emb + (size_t)__ldg(toks + (t+1)*Bz + b2)*512 + k2);
                __stcg(&g_embT[k2*64 + b2], ev);
            }
        }
        gridbar_to(++bgen);
    }
}

// ---------------------------------------------------------------------------
extern "C" void kernel_launch(void* const* d_in, const int* in_sizes, int n_in,
                              void* d_out, int out_size)
{
    const int*   toks = (const int*)  d_in[0];
    // d_in[1] = src (unused by the reference computation)
    const float* ctx  = (const float*)d_in[2];
    const float* h0   = (const float*)d_in[3];
    const float* c0   = (const float*)d_in[4];
    const float* feed = (const float*)d_in[5];
    const float* emb  = (const float*)d_in[6];
    const float* Wih0 = (const float*)d_in[7];
    const float* Whh0 = (const float*)d_in[8];
    const float* bih0 = (const float*)d_in[9];
    const float* bhh0 = (const float*)d_in[10];
    const float* Wih1 = (const float*)d_in[11];
    const float* Whh1 = (const float*)d_in[12];
    const float* bih1 = (const float*)d_in[13];
    const float* bhh1 = (const float*)d_in[14];
    const float* Wa   = (const float*)d_in[15];
    const float* Wout = (const float*)d_in[16];
    float* dout = (float*)d_out;

    const int shmem = 13440 * 4;   // 53.76 KB dynamic
    static int attr_set = 0;
    if (!attr_set){
        cudaFuncSetAttribute(kMain, cudaFuncAttributeMaxDynamicSharedMemorySize, shmem);
        attr_set = 1;
    }
    kMain<<<NB, NT, shmem>>>(toks, ctx, h0, c0, feed, emb,
                             Wih0, Whh0, bih0, bhh0,
                             Wih1, Whh1, bih1, bhh1,
                             Wa, Wout, dout);
}